// round 17
// baseline (speedup 1.0000x reference)
#include <cuda_runtime.h>
#include <cuda_fp16.h>
#include <math.h>
#include <stdint.h>

// ---------------- problem constants ----------------
#define Bn 2
#define Tn 2048
#define NH 16
#define NKV 4
#define HD 128
#define DMODEL 2048
#define KVDIM 512
#define QKVSTR 3072         // combined QKV row: Q[0:2048) K[2048:2560) V[2560:3072)
#define ROWS 4096           // Bn*Tn
#define GK 2048             // K dim of every GEMM

// ---------------- scratch (__device__ globals) ----------------
__device__ __half g_xh  [(size_t)ROWS * DMODEL];  // fp16 x
__device__ __half g_QKVh[(size_t)ROWS * QKVSTR];  // fp16 roped Q,K; V region unused
__device__ __half g_Vh  [(size_t)ROWS * KVDIM];   // V fp16: [b][kvh][t][d]
__device__ __half g_Oh  [(size_t)ROWS * DMODEL];  // flash output fp16
__device__ __half g_wh  [(size_t)GK * QKVSTR];    // fused [wq|wk|wv] fp16, natural [K][N]
__device__ __half g_woh [(size_t)GK * DMODEL];    // wo fp16, natural [K][N]
__device__ float2 g_rt  [Tn * 64];                // rope table: (cos, sin)

// ---------------- PTX helpers (baseline sm_80+ only) ----------------
__device__ __forceinline__ uint32_t smem_u32(const void* p) {
    uint32_t a;
    asm("{ .reg .u64 t; cvta.to.shared.u64 t, %1; cvt.u32.u64 %0, t; }" : "=r"(a) : "l"(p));
    return a;
}
__device__ __forceinline__ uint32_t packh2(float lo, float hi) {   // {lo,hi} fp16x2
    uint32_t r; asm("cvt.rn.f16x2.f32 %0, %1, %2;" : "=r"(r) : "f"(hi), "f"(lo)); return r;
}
__device__ __forceinline__ uint32_t ex2h2(uint32_t x) {            // 2^x on both halves
    uint32_t r; asm("ex2.approx.f16x2 %0, %1;" : "=r"(r) : "r"(x)); return r;
}
__device__ __forceinline__ uint32_t swz(uint32_t off) {   // SW128: bits[6:4] ^= bits[9:7]
    return off ^ ((off >> 3) & 0x70);
}
__device__ __forceinline__ void cp16(uint32_t dst, const void* src) {
    asm volatile("cp.async.cg.shared.global [%0], [%1], 16;" :: "r"(dst), "l"(src) : "memory");
}
#define CP_COMMIT() asm volatile("cp.async.commit_group;" ::: "memory")
#define CP_WAIT(n)  asm volatile("cp.async.wait_group %0;" :: "n"(n) : "memory")

__device__ __forceinline__ void ldsm_x4(uint32_t* r, uint32_t addr) {
    asm volatile("ldmatrix.sync.aligned.m8n8.x4.shared.b16 {%0,%1,%2,%3}, [%4];"
                 : "=r"(r[0]), "=r"(r[1]), "=r"(r[2]), "=r"(r[3]) : "r"(addr));
}
__device__ __forceinline__ void ldsm_x4_trans(uint32_t* r, uint32_t addr) {
    asm volatile("ldmatrix.sync.aligned.m8n8.x4.trans.shared.b16 {%0,%1,%2,%3}, [%4];"
                 : "=r"(r[0]), "=r"(r[1]), "=r"(r[2]), "=r"(r[3]) : "r"(addr));
}
__device__ __forceinline__ void mma_f16(float* d, const uint32_t* a, const uint32_t* b) {
    asm volatile(
        "mma.sync.aligned.m16n8k16.row.col.f32.f16.f16.f32 "
        "{%0,%1,%2,%3}, {%4,%5,%6,%7}, {%8,%9}, {%0,%1,%2,%3};"
        : "+f"(d[0]), "+f"(d[1]), "+f"(d[2]), "+f"(d[3])
        : "r"(a[0]), "r"(a[1]), "r"(a[2]), "r"(a[3]), "r"(b[0]), "r"(b[1]));
}

// ---------------- fused prep: streaming converts + rope table -------------
#define PREP_BLOCKS 18944

__global__ void prep_kernel(const float* __restrict__ x,
                            const float* __restrict__ wq, const float* __restrict__ wk,
                            const float* __restrict__ wv, const float* __restrict__ wo,
                            __half* __restrict__ xh) {
    int blk = blockIdx.x;
    int tid = threadIdx.x;
    if (blk < 10240) {
        const float* src; __half* dstbase; int nchunks_row, dststride, col0, c;
        if (blk < 4096)      { src = wq; dstbase = g_wh;  nchunks_row = 512; dststride = QKVSTR; col0 = 0;    c = blk * 256 + tid; }
        else if (blk < 5120) { src = wk; dstbase = g_wh;  nchunks_row = 128; dststride = QKVSTR; col0 = 2048; c = (blk - 4096) * 256 + tid; }
        else if (blk < 6144) { src = wv; dstbase = g_wh;  nchunks_row = 128; dststride = QKVSTR; col0 = 2560; c = (blk - 5120) * 256 + tid; }
        else                 { src = wo; dstbase = g_woh; nchunks_row = 512; dststride = DMODEL; col0 = 0;    c = (blk - 6144) * 256 + tid; }
        int k = c / nchunks_row;
        int n = (c % nchunks_row) * 4;
        float4 v = ((const float4*)src)[c];
        uint2 u;
        u.x = packh2(v.x, v.y);
        u.y = packh2(v.z, v.w);
        *(uint2*)(dstbase + (size_t)k * dststride + col0 + n) = u;
    } else if (blk < 18432) {
        int i = (blk - 10240) * 256 + tid;
        float4 v = ((const float4*)x)[i];
        uint2 u;
        u.x = packh2(v.x, v.y);
        u.y = packh2(v.z, v.w);
        ((uint2*)xh)[i] = u;
    } else {
        int e = (blk - 18432) * 256 + tid;   // e < 131072
        int tt = e >> 6, d = e & 63;
        float invf = (float)exp(-((double)d / 64.0) * log(10000.0));
        float ang = (float)tt * invf;
        float sn, cs;
        sincosf(ang, &sn, &cs);
        g_rt[e] = make_float2(cs, sn);
    }
}

// ---------------- fp16 mma.sync GEMM; MODE 1 epilogue fuses RoPE ----------
// C[M,N] = A[M,2048] @ W[2048,N], fp16 in; W natural [K][N] via trans-ldsm.
// Block 128x128, BK=64, 3-stage cp.async, 8 warps (2x4), warp 64x32, occ 2.
// MODE 0: fp32 out row-major. MODE 1: nb<2560 -> rope (via smem exchange) +
// fp16 QKVh; nb>=2560 -> fp16 V scatter.
#define BM 128
#define BN 128
#define NSTG 3
#define ASTG 16384
#define BSTG 16384
#define STG  (ASTG + BSTG)
#define GEMM_SMEM (NSTG * STG)   // 98304
#define KITERS 32

template <int MODE>
__global__ __launch_bounds__(256, 2)
void gemm_mma(const __half* __restrict__ A, const __half* __restrict__ W,
              void* __restrict__ Cout, int N) {
    extern __shared__ char dsm[];
    const uint32_t base = smem_u32(dsm);

    const int tid  = threadIdx.x;
    const int wid  = tid >> 5;
    const int lane = tid & 31;
    const int mb   = blockIdx.y * BM;
    const int nb   = blockIdx.x * BN;
    const int wm   = (wid & 1) * 64;
    const int wn   = (wid >> 1) * 32;

    const __half* Ag = A + (size_t)mb * GK;
    const __half* Wg = W + nb;               // [K][N] natural layout

    float acc[4][4][4];
#pragma unroll
    for (int mt = 0; mt < 4; mt++)
#pragma unroll
        for (int nt = 0; nt < 4; nt++)
#pragma unroll
            for (int q = 0; q < 4; q++) acc[mt][nt][q] = 0.f;

    auto issue = [&](int buf, int s) {
        uint32_t sa = base + (uint32_t)buf * STG;
        uint32_t sb = sa + ASTG;
        int k0 = s * 64;
#pragma unroll
        for (int i = 0; i < 4; i++) {          // A: 1024 chunks
            int cc  = tid + i * 256;
            int row = cc >> 3, ch = cc & 7;
            cp16(sa + swz((uint32_t)(row * 128 + ch * 16)),
                 Ag + (size_t)row * GK + k0 + ch * 8);
        }
#pragma unroll
        for (int i = 0; i < 4; i++) {          // B: 1024 chunks ([64 k][128 n])
            int cc  = tid + i * 256;
            int kr = cc >> 4, ch = cc & 15;
            cp16(sb + (uint32_t)((ch >> 3) * 8192) + swz((uint32_t)(kr * 128 + (ch & 7) * 16)),
                 Wg + (size_t)(k0 + kr) * N + ch * 8);
        }
        CP_COMMIT();
    };

    issue(0, 0); issue(1, 1);

    const int a_r  = (lane & 7) + ((lane >> 3) & 1) * 8;
    const int a_kc = (lane >> 4);
    const int vrow = lane & 7;
    const int vmi  = lane >> 3;

    int st = 0, stp = 2;
    for (int s = 0; s < KITERS; s++) {
        if (s + 2 < KITERS) CP_WAIT(1); else CP_WAIT(0);
        __syncthreads();
        if (s + 2 < KITERS) issue(stp, s + 2);

        uint32_t sa = base + (uint32_t)st * STG + (uint32_t)(wm * 128);
        uint32_t sb = base + (uint32_t)st * STG + ASTG;

#pragma unroll
        for (int ks = 0; ks < 4; ks++) {
            uint32_t afr[4][4];
            uint32_t bfr[4][2];
#pragma unroll
            for (int mt = 0; mt < 4; mt++)
                ldsm_x4(afr[mt], sa + swz((uint32_t)((mt * 16 + a_r) * 128 + (2 * ks + a_kc) * 16)));
            {
                int vkey = ks * 16 + (vmi & 1) * 8 + vrow;
#pragma unroll
                for (int j = 0; j < 2; j++) {
                    int npp = (wn >> 3) + 2 * j + (vmi >> 1);
                    uint32_t tmp[4];
                    ldsm_x4_trans(tmp, sb + (uint32_t)((npp >> 3) * 8192)
                                         + swz((uint32_t)(vkey * 128 + (npp & 7) * 16)));
                    bfr[2 * j][0] = tmp[0]; bfr[2 * j][1] = tmp[1];
                    bfr[2 * j + 1][0] = tmp[2]; bfr[2 * j + 1][1] = tmp[3];
                }
            }
#pragma unroll
            for (int mt = 0; mt < 4; mt++)
#pragma unroll
                for (int nt = 0; nt < 4; nt++)
                    mma_f16(acc[mt][nt], afr[mt], bfr[nt]);
        }
        st  = (st  == NSTG - 1) ? 0 : st + 1;
        stp = (stp == NSTG - 1) ? 0 : stp + 1;
    }

    const int g = lane >> 2;
    const int cq = (lane & 3) * 2;

    if (MODE == 1 && nb < 2560) {
        // ---- fused RoPE epilogue: one head per block; pairs (d, d+64) via smem
        float* cs = (float*)dsm;            // tile [128][132] fp32
        __syncthreads();                    // mma loop fully done; smem reusable
#pragma unroll
        for (int mt = 0; mt < 4; mt++) {
            int lr = wm + mt * 16 + g;
#pragma unroll
            for (int nt = 0; nt < 4; nt++) {
                int c = wn + nt * 8 + cq;
                *(float2*)&cs[lr * 132 + c]       = make_float2(acc[mt][nt][0], acc[mt][nt][1]);
                *(float2*)&cs[(lr + 8) * 132 + c] = make_float2(acc[mt][nt][2], acc[mt][nt][3]);
            }
        }
        __syncthreads();
        __half* C = (__half*)Cout;
#pragma unroll
        for (int mt = 0; mt < 4; mt++) {
            int lr = wm + mt * 16 + g;
            int grow = mb + lr;
            int t0 = grow & (Tn - 1), t1 = (grow + 8) & (Tn - 1);
#pragma unroll
            for (int nt = 0; nt < 4; nt++) {
                int c = wn + nt * 8 + cq;
                float out0[2], out1[2];
#pragma unroll
                for (int j = 0; j < 2; j++) {
                    int col = c + j;
                    int dd = col & 63;
                    float2 cs0 = g_rt[(t0 << 6) + dd];
                    float2 cs1 = g_rt[(t1 << 6) + dd];
                    float p0 = cs[lr * 132 + (col ^ 64)];
                    float p1 = cs[(lr + 8) * 132 + (col ^ 64)];
                    if (col < 64) {
                        out0[j] = acc[mt][nt][j]     * cs0.x - p0 * cs0.y;
                        out1[j] = acc[mt][nt][2 + j] * cs1.x - p1 * cs1.y;
                    } else {
                        out0[j] = acc[mt][nt][j]     * cs0.x + p0 * cs0.y;
                        out1[j] = acc[mt][nt][2 + j] * cs1.x + p1 * cs1.y;
                    }
                }
                uint32_t w0 = packh2(out0[0], out0[1]);
                uint32_t w1 = packh2(out1[0], out1[1]);
                *(uint32_t*)(C + (size_t)grow * QKVSTR + nb + c)       = w0;
                *(uint32_t*)(C + (size_t)(grow + 8) * QKVSTR + nb + c) = w1;
            }
        }
        return;
    }

#pragma unroll
    for (int mt = 0; mt < 4; mt++) {
        int row0 = mb + wm + mt * 16 + g;
#pragma unroll
        for (int nt = 0; nt < 4; nt++) {
            int col = nb + wn + nt * 8 + cq;
            if (MODE == 0) {
                float* C = (float*)Cout;
                *(float2*)(C + (size_t)row0 * N + col)       = make_float2(acc[mt][nt][0], acc[mt][nt][1]);
                *(float2*)(C + (size_t)(row0 + 8) * N + col) = make_float2(acc[mt][nt][2], acc[mt][nt][3]);
            } else {   // V scatter
                uint32_t w0 = packh2(acc[mt][nt][0], acc[mt][nt][1]);
                uint32_t w1 = packh2(acc[mt][nt][2], acc[mt][nt][3]);
                int rel = col - 2560;
                int kvh = rel >> 7, d = rel & 127;
                int b0 = row0 >> 11, t0 = row0 & (Tn - 1);
                int b1 = (row0 + 8) >> 11, t1 = (row0 + 8) & (Tn - 1);
                *(uint32_t*)(g_Vh + (((size_t)(b0 * NKV + kvh) * Tn + t0) * HD + d)) = w0;
                *(uint32_t*)(g_Vh + (((size_t)(b1 * NKV + kvh) * Tn + t1) * HD + d)) = w1;
            }
        }
    }
}

// ---------------- flash attention (R15 persistent config, unchanged) ------
#define FM 64
#define FN 64
#define KVBUF 32768
#define FLASH_SMEM (16384 + 2 * KVBUF)   // 81920
#define FTHREADS 128
#define NJOBS 1024
#define NPERS 296

__global__ __launch_bounds__(FTHREADS, 2)
void flash_mma(const __half* __restrict__ QKVh, const __half* __restrict__ Vh,
               __half* __restrict__ Oh) {
    extern __shared__ float sm[];
    const uint32_t base = smem_u32(sm);
    const int tid = threadIdx.x, wid = tid >> 5, lane = tid & 31;

    const int a_r  = (lane & 7) + ((lane >> 3) & 1) * 8;
    const int a_kc = lane >> 4;
    const int b_r  = (lane & 7) + (lane >> 4) * 8;
    const int b_kc = (lane >> 3) & 1;
    const int g    = lane >> 2;
    const int cq2  = (lane & 3) * 2;
    const int vrow = lane & 7;
    const int vmi  = lane >> 3;
    const float scale2 = 0.08838834764831843f * 1.4426950408889634f;
    const uint32_t ONESx2 = 0x3C003C00u;
    const uint32_t bones[2] = {ONESx2, ONESx2};

    for (int job = blockIdx.x; job < NJOBS; job += NPERS) {
        const int qb = 31 - (job >> 5);
        const int hb = job & 31;
        const int h = hb & 15, b = hb >> 4;
        const int kvh = h >> 2;
        const int nkt = qb + 1;

        const __half* Qg = QKVh + ((size_t)(b * Tn + qb * FM)) * QKVSTR + h * HD;
        const __half* Kg = QKVh + ((size_t)(b * Tn)) * QKVSTR + 2048 + kvh * HD;
        const __half* Vg = Vh + ((size_t)(b * NKV + kvh)) * Tn * HD;

        __syncthreads();

#pragma unroll
        for (int i = 0; i < 8; i++) {
            int f = tid + i * FTHREADS;
            int qr = f >> 4, ch = f & 15;
            cp16(base + (uint32_t)((ch >> 3) * 8192) + swz((uint32_t)(qr * 128 + (ch & 7) * 16)),
                 Qg + (size_t)qr * QKVSTR + ch * 8);
        }

        auto kv_issue = [&](int kt) {
            uint32_t kb = base + 16384u + (uint32_t)(kt & 1) * KVBUF;
            uint32_t vb = kb + 16384u;
            const __half* Ksrc = Kg + (size_t)(kt * FN) * QKVSTR;
            const __half* Vsrc = Vg + (size_t)(kt * FN) * HD;
#pragma unroll
            for (int i = 0; i < 8; i++) {
                int f = tid + i * FTHREADS;
                int kr = f >> 4, ch = f & 15;
                cp16(kb + (uint32_t)((ch >> 3) * 8192) + swz((uint32_t)(kr * 128 + (ch & 7) * 16)),
                     Ksrc + (size_t)kr * QKVSTR + ch * 8);
            }
#pragma unroll
            for (int i = 0; i < 8; i++) {
                int f = tid + i * FTHREADS;
                int key = f >> 4, ch = f & 15;
                cp16(vb + (uint32_t)((ch >> 3) * 8192) + swz((uint32_t)(key * 128 + (ch & 7) * 16)),
                     Vsrc + key * HD + ch * 8);
            }
            CP_COMMIT();
        };

        float o[16][4];
#pragma unroll
        for (int nt = 0; nt < 16; nt++)
#pragma unroll
            for (int q = 0; q < 4; q++) o[nt][q] = 0.f;
        float lacc[4] = {0.f, 0.f, 0.f, 0.f};
        float m0 = -1e30f, m1 = -1e30f;

        kv_issue(0);

        for (int kt = 0; kt < nkt; kt++) {
            __syncthreads();
            if (kt + 1 < nkt) { kv_issue(kt + 1); CP_WAIT(1); }
            else              { CP_WAIT(0); }
            __syncthreads();

            uint32_t kb = base + 16384u + (uint32_t)(kt & 1) * KVBUF;
            uint32_t vb = kb + 16384u;

            float sacc[8][4];
#pragma unroll
            for (int nt = 0; nt < 8; nt++)
#pragma unroll
                for (int q = 0; q < 4; q++) sacc[nt][q] = 0.f;

#pragma unroll
            for (int ks = 0; ks < 8; ks++) {
                uint32_t af[4];
                ldsm_x4(af, base + (uint32_t)((ks >> 2) * 8192)
                            + swz((uint32_t)((wid * 16 + a_r) * 128 + ((ks & 3) * 2 + a_kc) * 16)));
                uint32_t bf[8][2];
#pragma unroll
                for (int np = 0; np < 4; np++) {
                    uint32_t tmp[4];
                    ldsm_x4(tmp, kb + (uint32_t)((ks >> 2) * 8192)
                                 + swz((uint32_t)((np * 16 + b_r) * 128 + ((ks & 3) * 2 + b_kc) * 16)));
                    bf[np * 2][0] = tmp[0]; bf[np * 2][1] = tmp[1];
                    bf[np * 2 + 1][0] = tmp[2]; bf[np * 2 + 1][1] = tmp[3];
                }
#pragma unroll
                for (int nt = 0; nt < 8; nt++) mma_f16(sacc[nt], af, bf[nt]);
            }

            if (kt == qb) {
                int rl0 = wid * 16 + g, rl1 = rl0 + 8;
#pragma unroll
                for (int nt = 0; nt < 8; nt++) {
                    int kc0 = nt * 8 + cq2;
                    sacc[nt][0] = (kc0     > rl0) ? -1e30f : sacc[nt][0] * scale2;
                    sacc[nt][1] = (kc0 + 1 > rl0) ? -1e30f : sacc[nt][1] * scale2;
                    sacc[nt][2] = (kc0     > rl1) ? -1e30f : sacc[nt][2] * scale2;
                    sacc[nt][3] = (kc0 + 1 > rl1) ? -1e30f : sacc[nt][3] * scale2;
                }
            } else {
#pragma unroll
                for (int nt = 0; nt < 8; nt++)
#pragma unroll
                    for (int q = 0; q < 4; q++) sacc[nt][q] *= scale2;
            }

            float mx0 = -1e30f, mx1 = -1e30f;
#pragma unroll
            for (int nt = 0; nt < 8; nt++) {
                mx0 = fmaxf(mx0, fmaxf(sacc[nt][0], sacc[nt][1]));
                mx1 = fmaxf(mx1, fmaxf(sacc[nt][2], sacc[nt][3]));
            }
            mx0 = fmaxf(mx0, __shfl_xor_sync(0xffffffffu, mx0, 1));
            mx0 = fmaxf(mx0, __shfl_xor_sync(0xffffffffu, mx0, 2));
            mx1 = fmaxf(mx1, __shfl_xor_sync(0xffffffffu, mx1, 1));
            mx1 = fmaxf(mx1, __shfl_xor_sync(0xffffffffu, mx1, 2));
            float nm0 = fmaxf(m0, mx0), nm1 = fmaxf(m1, mx1);
            float al0 = exp2f(m0 - nm0), al1 = exp2f(m1 - nm1);
            m0 = nm0; m1 = nm1;

            uint32_t pf[4][4];
#pragma unroll
            for (int kc = 0; kc < 4; kc++) {
                pf[kc][0] = ex2h2(packh2(sacc[2 * kc][0] - nm0,     sacc[2 * kc][1] - nm0));
                pf[kc][1] = ex2h2(packh2(sacc[2 * kc][2] - nm1,     sacc[2 * kc][3] - nm1));
                pf[kc][2] = ex2h2(packh2(sacc[2 * kc + 1][0] - nm0, sacc[2 * kc + 1][1] - nm0));
                pf[kc][3] = ex2h2(packh2(sacc[2 * kc + 1][2] - nm1, sacc[2 * kc + 1][3] - nm1));
            }

#pragma unroll
            for (int nt = 0; nt < 16; nt++) {
                o[nt][0] *= al0; o[nt][1] *= al0;
                o[nt][2] *= al1; o[nt][3] *= al1;
            }
            lacc[0] *= al0; lacc[1] *= al0;
            lacc[2] *= al1; lacc[3] *= al1;

#pragma unroll
            for (int kc = 0; kc < 4; kc++) mma_f16(lacc, pf[kc], bones);

#pragma unroll
            for (int kc = 0; kc < 4; kc++) {
                int vkey = kc * 16 + (vmi & 1) * 8 + vrow;
#pragma unroll
                for (int np = 0; np < 16; np += 2) {
                    int npp = np + (vmi >> 1);
                    uint32_t tmp[4];
                    ldsm_x4_trans(tmp, vb + (uint32_t)((npp >> 3) * 8192)
                                          + swz((uint32_t)(vkey * 128 + (npp & 7) * 16)));
                    mma_f16(o[np],     pf[kc], tmp);
                    mma_f16(o[np + 1], pf[kc], tmp + 2);
                }
            }
        }

        float il0 = 1.f / lacc[0], il1 = 1.f / lacc[2];
        __half* Ob = Oh + ((size_t)(b * Tn + qb * FM + wid * 16)) * DMODEL + h * HD;
#pragma unroll
        for (int nt = 0; nt < 16; nt++) {
            int col = nt * 8 + cq2;
            uint32_t w0 = packh2(o[nt][0] * il0, o[nt][1] * il0);
            uint32_t w1 = packh2(o[nt][2] * il1, o[nt][3] * il1);
            *(uint32_t*)(Ob + (size_t)g * DMODEL + col)       = w0;
            *(uint32_t*)(Ob + (size_t)(g + 8) * DMODEL + col) = w1;
        }
    }
}

// ---------------- launch ----------------
extern "C" void kernel_launch(void* const* d_in, const int* in_sizes, int n_in,
                              void* d_out, int out_size) {
    (void)in_sizes; (void)n_in; (void)out_size;
    const float* x  = (const float*)d_in[0];
    const float* wq = (const float*)d_in[1];
    const float* wk = (const float*)d_in[2];
    const float* wv = (const float*)d_in[3];
    const float* wo = (const float*)d_in[4];
    float* out = (float*)d_out;

    __half *xh, *QKVh, *Vh, *Oh, *wh, *woh;
    cudaGetSymbolAddress((void**)&xh,   g_xh);
    cudaGetSymbolAddress((void**)&QKVh, g_QKVh);
    cudaGetSymbolAddress((void**)&Vh,   g_Vh);
    cudaGetSymbolAddress((void**)&Oh,   g_Oh);
    cudaGetSymbolAddress((void**)&wh,   g_wh);
    cudaGetSymbolAddress((void**)&woh,  g_woh);

    cudaFuncSetAttribute(flash_mma,   cudaFuncAttributeMaxDynamicSharedMemorySize, FLASH_SMEM);
    cudaFuncSetAttribute(gemm_mma<0>, cudaFuncAttributeMaxDynamicSharedMemorySize, GEMM_SMEM);
    cudaFuncSetAttribute(gemm_mma<1>, cudaFuncAttributeMaxDynamicSharedMemorySize, GEMM_SMEM);

    // prep: streaming fp16 converts + rope table
    prep_kernel<<<PREP_BLOCKS, 256>>>(x, wq, wk, wv, wo, xh);

    // Fused QKV projection with in-epilogue RoPE (Q,K) and V scatter
    gemm_mma<1><<<dim3(QKVSTR / BN, ROWS / BM), 256, GEMM_SMEM>>>(xh, wh, QKVh, QKVSTR);

    // Causal attention (persistent)
    flash_mma<<<NPERS, FTHREADS, FLASH_SMEM>>>(QKVh, Vh, Oh);

    // Output projection (fp32 out)
    gemm_mma<0><<<dim3(DMODEL / BN, ROWS / BM), 256, GEMM_SMEM>>>(Oh, woh, out, DMODEL);
}